// round 6
// baseline (speedup 1.0000x reference)
#include <cuda_runtime.h>
#include <cstdint>
#include <math.h>

#define BATCH 64
#define SEQ   512
#define INSZ  512
#define HSZ   512
#define G4    2048   // 4*HSZ
#define NCTA  128
#define GRP   32     // CTAs per bt-group
#define REPLAY_E (SEQ + 1)

// ---------------- scratch (device globals; no allocation allowed) ----------
__device__ float g_xproj[(size_t)BATCH * SEQ * G4];   // x @ W_ih, row = b*SEQ+t
__device__ float g_hT[2][HSZ * BATCH];                // transposed hidden state: [j][b]
__device__ unsigned g_cnt4[4][32];                    // per-group ticket counters (128B apart)
__device__ unsigned g_flag[4][32][32];                // [bt][jt][pad]: epoch flags, 128B apart

// ---------------- f32x2 packed math helpers (sm_103a) ----------------------
__device__ __forceinline__ unsigned long long pack2(float lo, float hi) {
    unsigned long long r;
    asm("mov.b64 %0, {%1, %2};" : "=l"(r) : "f"(lo), "f"(hi));
    return r;
}
__device__ __forceinline__ void unpack2(unsigned long long v, float& lo, float& hi) {
    asm("mov.b64 {%0, %1}, %2;" : "=f"(lo), "=f"(hi) : "l"(v));
}
__device__ __forceinline__ unsigned long long ffma2(unsigned long long a,
                                                    unsigned long long b,
                                                    unsigned long long c) {
    unsigned long long d;
    asm("fma.rn.f32x2 %0, %1, %2, %3;" : "=l"(d) : "l"(a), "l"(b), "l"(c));
    return d;
}

// ---------------- acquire/release flag ops ---------------------------------
__device__ __forceinline__ unsigned ld_acq(const unsigned* p) {
    unsigned v;
    asm volatile("ld.acquire.gpu.u32 %0, [%1];" : "=r"(v) : "l"(p) : "memory");
    return v;
}
__device__ __forceinline__ void st_rel(unsigned* p, unsigned v) {
    asm volatile("st.release.gpu.u32 [%0], %1;" :: "l"(p), "r"(v) : "memory");
}

// ---------------- fast activations (MUFU-based, rel err ~1e-6) -------------
__device__ __forceinline__ float ex2f(float x) {
    float y; asm("ex2.approx.f32 %0, %1;" : "=f"(y) : "f"(x)); return y;
}
__device__ __forceinline__ float rcpf(float x) {
    float y; asm("rcp.approx.f32 %0, %1;" : "=f"(y) : "f"(x)); return y;
}
#define LOG2E 1.4426950408889634f
__device__ __forceinline__ float fast_sigmoid(float x) {
    return rcpf(1.0f + ex2f(-x * LOG2E));
}
__device__ __forceinline__ float fast_tanh(float x) {
    float a = fabsf(x);
    float t = ex2f(-2.0f * LOG2E * a);
    float r = 1.0f - 2.0f * t * rcpf(1.0f + t);
    return copysignf(r, x);
}

// ---------------- kernel 1: x_proj = x @ W_ih ------------------------------
__global__ __launch_bounds__(256) void xproj_gemm(const float* __restrict__ X,
                                                  const float* __restrict__ Wih) {
    __shared__ float  As[16][64];    // [k][m]
    __shared__ float4 Bs[16][16];    // [k][n/4]

    const int tid = threadIdx.x;
    const int m0 = blockIdx.y * 64;
    const int n0 = blockIdx.x * 64;
    const int tx = tid % 16;
    const int ty = tid / 16;

    unsigned long long acc[4][2];
#pragma unroll
    for (int i = 0; i < 4; i++) { acc[i][0] = 0ull; acc[i][1] = 0ull; }

    const int arow = tid / 4;
    const int acg  = (tid % 4) * 4;
    const int brow = tid / 16;
    const int bcg  = tid % 16;

    for (int k0 = 0; k0 < INSZ; k0 += 16) {
        float4 av = *(const float4*)&X[(size_t)(m0 + arow) * INSZ + k0 + acg];
        As[acg + 0][arow] = av.x;
        As[acg + 1][arow] = av.y;
        As[acg + 2][arow] = av.z;
        As[acg + 3][arow] = av.w;
        Bs[brow][bcg] = *(const float4*)&Wih[(size_t)(k0 + brow) * G4 + n0 + bcg * 4];
        __syncthreads();

        const unsigned long long* Bs2 = (const unsigned long long*)Bs;
#pragma unroll
        for (int kk = 0; kk < 16; kk++) {
            unsigned long long b0 = Bs2[kk * 32 + tx * 2 + 0];
            unsigned long long b1 = Bs2[kk * 32 + tx * 2 + 1];
#pragma unroll
            for (int i = 0; i < 4; i++) {
                float a = As[kk][ty * 4 + i];
                unsigned long long pa = pack2(a, a);
                acc[i][0] = ffma2(pa, b0, acc[i][0]);
                acc[i][1] = ffma2(pa, b1, acc[i][1]);
            }
        }
        __syncthreads();
    }

#pragma unroll
    for (int i = 0; i < 4; i++) {
        float x0, x1, x2, x3;
        unpack2(acc[i][0], x0, x1);
        unpack2(acc[i][1], x2, x3);
        float4 v = make_float4(x0, x1, x2, x3);
        *(float4*)&g_xproj[(size_t)(m0 + ty * 4 + i) * G4 + n0 + tx * 4] = v;
    }
}

// ---------------- kernel 2: persistent LSTM, distributed flag sync ---------
// 128 CTAs (1/SM). Per step, warp wid consumes h only from producer CTAs
// jt' in [wid*4, wid*4+4): it polls those 4 epoch flags (acquire), stages its
// own k-slice warp-locally, and gemms. After reduce+update, the CTA publishes
// its h slice with a release flag store. No global barrier anywhere.
__global__ __launch_bounds__(256, 1) void lstm_persist(
    const float* __restrict__ Whh, const float* __restrict__ bias,
    const float* __restrict__ h0,  const float* __restrict__ c0,
    float* __restrict__ out) {
    extern __shared__ float smem[];
    float2*   W2  = (float2*)smem;          // [k][jl*2+gp] 128KB
    float*    hsT = smem + 32768;           // [k][b]        32KB
    float*    red = smem + 32768 + 8192;    // [warp][gate][b][jl] 32KB
    unsigned* sR  = (unsigned*)(smem + 32768 + 8192 + 8192);

    const int tid  = threadIdx.x;
    const int wid  = tid >> 5;
    const int lane = tid & 31;
    const int jt = blockIdx.x & 31, bt = blockIdx.x >> 5;
    const int j0 = jt * 16, b0 = bt * 16;

    // --- update-thread identity: one (b, j) output per thread ---
    const int bl = tid >> 4, jl_u = tid & 15;
    const int b = b0 + bl, j = j0 + jl_u;

    // --- init h state slice ---
    __stcg(&g_hT[0][j * BATCH + b], h0[(size_t)b * HSZ + j]);

    // --- load W slice once ---
    for (int idx = tid; idx < 512 * 16; idx += 256) {
        int k = idx >> 4, jl = idx & 15;
        const float* wr = Whh + (size_t)k * G4 + j0 + jl;
        W2[k * 32 + jl * 2 + 0] = make_float2(wr[0],       wr[HSZ]);
        W2[k * 32 + jl * 2 + 1] = make_float2(wr[2 * HSZ], wr[3 * HSZ]);
    }

    float cc = c0[(size_t)b * HSZ + j];
    const float bi = bias[j], bf = bias[j + HSZ];
    const float bg = bias[j + 2 * HSZ], bo = bias[j + 3 * HSZ];

    // --- compute identity: warp owns k-slice, lane owns (jl, gate-pair) ---
    const int ks0 = wid * 64;
    const int jl_c = lane >> 1, gp = lane & 1;
    float* rA = &red[((wid * 4 + gp * 2 + 0) * 16) * 16 + jl_c];
    float* rB = &red[((wid * 4 + gp * 2 + 1) * 16) * 16 + jl_c];

    // --- epoch base: monotonic ticket, identical across the bt group -------
    __syncthreads();   // h0 stores + W loads done
    if (tid == 0) {
        unsigned tk = atomicAdd(&g_cnt4[bt][0], 1u) + 1u;
        unsigned R = (tk + (GRP - 1)) / GRP;          // replay round, same for group
        sR[0] = (R - 1) * REPLAY_E;                   // epoch base E0
        __threadfence();
        st_rel(&g_flag[bt][jt][0], (R - 1) * REPLAY_E + 1);   // h_0 published
    }
    __syncthreads();
    const unsigned E0 = sR[0];

    for (int t = 0; t < SEQ; t++) {
        const int cur = t & 1;
        const float* hin = g_hT[cur];

        // prefetch this step's x_proj contribution (consumed post-gemm)
        const float* xp = g_xproj + ((size_t)b * SEQ + t) * G4 + j;
        float xi = __ldg(xp);
        float xf = __ldg(xp + HSZ);
        float xg = __ldg(xp + 2 * HSZ);
        float xo = __ldg(xp + 3 * HSZ);

        // --- wait only for this warp's 4 producer CTAs (h_t published) ---
        const unsigned Ft = E0 + (unsigned)t + 1u;
        if (lane < 4) {
            const unsigned* fp = &g_flag[bt][wid * 4 + lane][0];
            while (ld_acq(fp) < Ft) { }
        }
        __syncwarp();

        // --- stage this warp's own k-slice (warp-local; no block sync) ---
#pragma unroll
        for (int it = 0; it < 8; it++) {
            int lin = wid * 256 + it * 32 + lane;    // float4 slot within slice
            int k = lin >> 2, b4 = (lin & 3) << 2;
            float4 v = __ldcg((const float4*)&hin[k * BATCH + b0 + b4]);
            *(float4*)&hsT[k * 16 + b4] = v;
        }
        __syncwarp();

        // --- GEMM slice: 16 f32x2 accumulators packed over batch pairs ---
        unsigned long long accA[8], accB[8];
#pragma unroll
        for (int p = 0; p < 8; p++) { accA[p] = 0ull; accB[p] = 0ull; }

#pragma unroll 4
        for (int k = ks0; k < ks0 + 64; k++) {
            float2 w = W2[k * 32 + lane];
            unsigned long long wa = pack2(w.x, w.x);
            unsigned long long wb = pack2(w.y, w.y);
            const ulonglong2* hp = (const ulonglong2*)&hsT[k * 16];
            ulonglong2 h01 = hp[0], h23 = hp[1], h45 = hp[2], h67 = hp[3];
            accA[0] = ffma2(h01.x, wa, accA[0]); accB[0] = ffma2(h01.x, wb, accB[0]);
            accA[1] = ffma2(h01.y, wa, accA[1]); accB[1] = ffma2(h01.y, wb, accB[1]);
            accA[2] = ffma2(h23.x, wa, accA[2]); accB[2] = ffma2(h23.x, wb, accB[2]);
            accA[3] = ffma2(h23.y, wa, accA[3]); accB[3] = ffma2(h23.y, wb, accB[3]);
            accA[4] = ffma2(h45.x, wa, accA[4]); accB[4] = ffma2(h45.x, wb, accB[4]);
            accA[5] = ffma2(h45.y, wa, accA[5]); accB[5] = ffma2(h45.y, wb, accB[5]);
            accA[6] = ffma2(h67.x, wa, accA[6]); accB[6] = ffma2(h67.x, wb, accB[6]);
            accA[7] = ffma2(h67.y, wa, accA[7]); accB[7] = ffma2(h67.y, wb, accB[7]);
        }

        // --- write split-K partials ---
#pragma unroll
        for (int p = 0; p < 8; p++) {
            float lo, hi;
            unpack2(accA[p], lo, hi);
            rA[(2 * p) * 16] = lo; rA[(2 * p + 1) * 16] = hi;
            unpack2(accB[p], lo, hi);
            rB[(2 * p) * 16] = lo; rB[(2 * p + 1) * 16] = hi;
        }
        __syncthreads();   // bar1: partials visible; also protects red reuse

        // --- reduce 8 warps + pointwise LSTM cell (fast activations) ---
        float si = 0.f, sf = 0.f, sg = 0.f, so = 0.f;
#pragma unroll
        for (int w = 0; w < 8; w++) {
            const float* rp = &red[((w * 4) * 16 + bl) * 16 + jl_u];
            si += rp[0];
            sf += rp[256];
            sg += rp[512];
            so += rp[768];
        }
        float gi = si + xi + bi, gf = sf + xf + bf;
        float gg = sg + xg + bg, go = so + xo + bo;
        float iv = fast_sigmoid(gi), fv = fast_sigmoid(gf);
        float gv = fast_tanh(gg),    ov = fast_sigmoid(go);
        cc = fv * cc + iv * gv;
        float hv = ov * fast_tanh(cc);

        // cross-CTA-visible h store first, then output
        __stcg(&g_hT[cur ^ 1][j * BATCH + b], hv);
        out[((size_t)b * SEQ + t) * HSZ + j] = hv;
        if (t == SEQ - 1) {
            out[(size_t)BATCH * SEQ * HSZ + (size_t)b * HSZ + j] = hv;
            out[(size_t)BATCH * SEQ * HSZ + BATCH * HSZ + (size_t)b * HSZ + j] = cc;
        }

        __syncthreads();   // bar2: all h stores done before publishing
        if (tid == 0) {
            st_rel(&g_flag[bt][jt][0], Ft + 1u);   // h_{t+1} published
        }
    }
}

// ---------------- launch ----------------------------------------------------
extern "C" void kernel_launch(void* const* d_in, const int* in_sizes, int n_in,
                              void* d_out, int out_size) {
    const float* x    = (const float*)d_in[0];
    const float* wih  = (const float*)d_in[1];
    const float* whh  = (const float*)d_in[2];
    const float* bias = (const float*)d_in[3];
    const float* h0   = (const float*)d_in[4];
    const float* c0   = (const float*)d_in[5];
    float* out = (float*)d_out;

    const int smem_bytes = 131072 + 32768 + 32768 + 128;   // 196736
    cudaFuncSetAttribute(lstm_persist, cudaFuncAttributeMaxDynamicSharedMemorySize,
                         smem_bytes);

    xproj_gemm<<<dim3(32, 512), 256>>>(x, wih);
    lstm_persist<<<NCTA, 256, smem_bytes>>>(whh, bias, h0, c0, out);
}

// round 8
// speedup vs baseline: 1.2684x; 1.2684x over previous
#include <cuda_runtime.h>
#include <cstdint>
#include <math.h>

#define BATCH 64
#define SEQ   512
#define INSZ  512
#define HSZ   512
#define G4    2048   // 4*HSZ
#define NCTA  128
#define GRP   32     // CTAs per bt-group barrier

// ---------------- scratch (device globals; no allocation allowed) ----------
__device__ float g_xproj[(size_t)BATCH * SEQ * G4];   // x @ W_ih, row = b*SEQ+t
__device__ float g_hT[2][HSZ * BATCH];                // transposed hidden state: [j][b]
__device__ unsigned g_cnt4[4][32];                    // 4 group counters, 128B apart

// ---------------- f32x2 packed math helpers (sm_103a) ----------------------
__device__ __forceinline__ unsigned long long pack2(float lo, float hi) {
    unsigned long long r;
    asm("mov.b64 %0, {%1, %2};" : "=l"(r) : "f"(lo), "f"(hi));
    return r;
}
__device__ __forceinline__ void unpack2(unsigned long long v, float& lo, float& hi) {
    asm("mov.b64 {%0, %1}, %2;" : "=f"(lo), "=f"(hi) : "l"(v));
}
__device__ __forceinline__ unsigned long long ffma2(unsigned long long a,
                                                    unsigned long long b,
                                                    unsigned long long c) {
    unsigned long long d;
    asm("fma.rn.f32x2 %0, %1, %2, %3;" : "=l"(d) : "l"(a), "l"(b), "l"(c));
    return d;
}

// ---------------- fast activations (MUFU-based, rel err ~1e-6) -------------
__device__ __forceinline__ float ex2f(float x) {
    float y; asm("ex2.approx.f32 %0, %1;" : "=f"(y) : "f"(x)); return y;
}
__device__ __forceinline__ float rcpf(float x) {
    float y; asm("rcp.approx.f32 %0, %1;" : "=f"(y) : "f"(x)); return y;
}
#define LOG2E 1.4426950408889634f
__device__ __forceinline__ float fast_sigmoid(float x) {
    return rcpf(1.0f + ex2f(-x * LOG2E));
}
__device__ __forceinline__ float fast_tanh(float x) {
    float a = fabsf(x);
    float t = ex2f(-2.0f * LOG2E * a);
    float r = 1.0f - 2.0f * t * rcpf(1.0f + t);
    return copysignf(r, x);
}

// ---------------- kernel 1: x_proj = x @ W_ih (v2 fixed: 128x128 tile) -----
// CTA tile 128(M) x 128(N), BK=16, 256 threads (tx=16 n-octets, ty=16 m-octets).
// Thread tile 8m x 8n. Acc pairs span M (A loads as LDS.128 from As[k][m], no
// dup MOVs). B staged PRE-DUPLICATED in SMEM as Bd[kk][n][tx]: each b load is
// a conflict-free LDS.64 (16 tx addresses = one 128B line, upper half bcast).
__global__ __launch_bounds__(256) void xproj_gemm(const float* __restrict__ X,
                                                  const float* __restrict__ Wih) {
    __shared__ float  As[16][128];     // [k][m]            8KB
    __shared__ float2 Bd[16][8][16];   // [k][n][tx] dup   16KB

    const int tid = threadIdx.x;
    const int m0 = blockIdx.y * 128;
    const int n0 = blockIdx.x * 128;
    const int tx = tid & 15;           // n: 8 cols at n0 + tx*8
    const int ty = tid >> 4;           // m: 8 rows at m0 + ty*8

    // staging identities
    const int arow = tid >> 1;           // 0..127
    const int akq  = (tid & 1) * 8;      // 0 or 8
    const int brow = tid >> 4;           // 0..15 (k within block)
    const int bcg  = tid & 15;           // n-octet owner

    unsigned long long acc[4][8];
#pragma unroll
    for (int p = 0; p < 4; p++)
#pragma unroll
        for (int n = 0; n < 8; n++) acc[p][n] = 0ull;

    for (int k0 = 0; k0 < INSZ; k0 += 16) {
        // stage A: 128 rows x 16 k (2 float4 per thread)
#pragma unroll
        for (int h = 0; h < 2; h++) {
            float4 av = *(const float4*)&X[(size_t)(m0 + arow) * INSZ + k0 + akq + h * 4];
            As[akq + h * 4 + 0][arow] = av.x;
            As[akq + h * 4 + 1][arow] = av.y;
            As[akq + h * 4 + 2][arow] = av.z;
            As[akq + h * 4 + 3][arow] = av.w;
        }
        // stage B duplicated: 16 k x 128 n (2 float4 per thread -> 8 dup pairs)
#pragma unroll
        for (int h = 0; h < 2; h++) {
            float4 bv = *(const float4*)&Wih[(size_t)(k0 + brow) * G4 + n0 + bcg * 8 + h * 4];
            Bd[brow][h * 4 + 0][bcg] = make_float2(bv.x, bv.x);
            Bd[brow][h * 4 + 1][bcg] = make_float2(bv.y, bv.y);
            Bd[brow][h * 4 + 2][bcg] = make_float2(bv.z, bv.z);
            Bd[brow][h * 4 + 3][bcg] = make_float2(bv.w, bv.w);
        }
        __syncthreads();

#pragma unroll
        for (int kk = 0; kk < 16; kk++) {
            ulonglong2 a01 = *(const ulonglong2*)&As[kk][ty * 8];
            ulonglong2 a23 = *(const ulonglong2*)&As[kk][ty * 8 + 4];
#pragma unroll
            for (int n = 0; n < 8; n++) {
                unsigned long long b = *(const unsigned long long*)&Bd[kk][n][tx];
                acc[0][n] = ffma2(a01.x, b, acc[0][n]);
                acc[1][n] = ffma2(a01.y, b, acc[1][n]);
                acc[2][n] = ffma2(a23.x, b, acc[2][n]);
                acc[3][n] = ffma2(a23.y, b, acc[3][n]);
            }
        }
        __syncthreads();
    }

    // epilogue: acc[p][n] = rows (m0+ty*8+2p, +1), col n0+tx*8+n
#pragma unroll
    for (int p = 0; p < 4; p++) {
        float lo[8], hi[8];
#pragma unroll
        for (int n = 0; n < 8; n++) unpack2(acc[p][n], lo[n], hi[n]);
        float* r0 = &g_xproj[(size_t)(m0 + ty * 8 + 2 * p) * G4 + n0 + tx * 8];
        float* r1 = r0 + G4;
        *(float4*)(r0)     = make_float4(lo[0], lo[1], lo[2], lo[3]);
        *(float4*)(r0 + 4) = make_float4(lo[4], lo[5], lo[6], lo[7]);
        *(float4*)(r1)     = make_float4(hi[0], hi[1], hi[2], hi[3]);
        *(float4*)(r1 + 4) = make_float4(hi[4], hi[5], hi[6], hi[7]);
    }
}

// ---------------- kernel 2: persistent LSTM recurrence (R5 proven) ---------
__global__ __launch_bounds__(256, 1) void lstm_persist(
    const float* __restrict__ Whh, const float* __restrict__ bias,
    const float* __restrict__ h0,  const float* __restrict__ c0,
    float* __restrict__ out) {
    extern __shared__ float smem[];
    float2* W2  = (float2*)smem;          // [k][jl*2+gp] 128KB
    float*  hsT = smem + 32768;           // [k][b]        32KB
    float*  red = smem + 32768 + 8192;    // [warp][gate][b][jl] 32KB

    const int tid  = threadIdx.x;
    const int wid  = tid >> 5;
    const int lane = tid & 31;
    const int jt = blockIdx.x & 31, bt = blockIdx.x >> 5;
    const int j0 = jt * 16, b0 = bt * 16;
    unsigned* cnt = &g_cnt4[bt][0];

    const int bl = tid >> 4, jl_u = tid & 15;
    const int b = b0 + bl, j = j0 + jl_u;

    // init h state slice
    __stcg(&g_hT[0][j * BATCH + b], h0[(size_t)b * HSZ + j]);

    // load W slice once: 512 k x 16 jl x 4 gates = 128KB
    for (int idx = tid; idx < 512 * 16; idx += 256) {
        int k = idx >> 4, jl = idx & 15;
        const float* wr = Whh + (size_t)k * G4 + j0 + jl;
        W2[k * 32 + jl * 2 + 0] = make_float2(wr[0],       wr[HSZ]);
        W2[k * 32 + jl * 2 + 1] = make_float2(wr[2 * HSZ], wr[3 * HSZ]);
    }

    float cc = c0[(size_t)b * HSZ + j];
    const float bi = bias[j], bf = bias[j + HSZ];
    const float bg = bias[j + 2 * HSZ], bo = bias[j + 3 * HSZ];

    const int ks0 = wid * 64;
    const int jl_c = lane >> 1, gp = lane & 1;
    float* rA = &red[((wid * 4 + gp * 2 + 0) * 16) * 16 + jl_c];
    float* rB = &red[((wid * 4 + gp * 2 + 1) * 16) * 16 + jl_c];

    // group barrier after init writes (monotonic counter: replay-safe)
    __syncthreads();
    if (tid == 0) {
        __threadfence();
        unsigned tk = atomicAdd(cnt, 1u) + 1u;
        unsigned target = (tk + (GRP - 1)) & ~(unsigned)(GRP - 1);
        while (*((volatile unsigned*)cnt) < target) { }
        __threadfence();
    }
    __syncthreads();

    for (int t = 0; t < SEQ; t++) {
        const int cur = t & 1;
        const float* hin = g_hT[cur];

        // prefetch this step's x_proj contribution (consumed post-gemm)
        const float* xp = g_xproj + ((size_t)b * SEQ + t) * G4 + j;
        float xi = __ldg(xp);
        float xf = __ldg(xp + HSZ);
        float xg = __ldg(xp + 2 * HSZ);
        float xo = __ldg(xp + 3 * HSZ);

        // stage h tile: [k][b] transposed layout, conflict-free, L2-coherent
#pragma unroll
        for (int it = 0; it < 8; it++) {
            int lin = tid + it * 256;            // float4 slot 0..2047
            int k = lin >> 2, b4 = (lin & 3) << 2;
            float4 v = __ldcg((const float4*)&hin[k * BATCH + b0 + b4]);
            *(float4*)&hsT[k * 16 + b4] = v;
        }
        __syncthreads();

        // GEMM slice: 16 f32x2 accumulators packed over batch pairs
        unsigned long long accA[8], accB[8];
#pragma unroll
        for (int p = 0; p < 8; p++) { accA[p] = 0ull; accB[p] = 0ull; }

#pragma unroll 4
        for (int k = ks0; k < ks0 + 64; k++) {
            float2 w = W2[k * 32 + lane];
            unsigned long long wa = pack2(w.x, w.x);
            unsigned long long wb = pack2(w.y, w.y);
            const ulonglong2* hp = (const ulonglong2*)&hsT[k * 16];
            ulonglong2 h01 = hp[0], h23 = hp[1], h45 = hp[2], h67 = hp[3];
            accA[0] = ffma2(h01.x, wa, accA[0]); accB[0] = ffma2(h01.x, wb, accB[0]);
            accA[1] = ffma2(h01.y, wa, accA[1]); accB[1] = ffma2(h01.y, wb, accB[1]);
            accA[2] = ffma2(h23.x, wa, accA[2]); accB[2] = ffma2(h23.x, wb, accB[2]);
            accA[3] = ffma2(h23.y, wa, accA[3]); accB[3] = ffma2(h23.y, wb, accB[3]);
            accA[4] = ffma2(h45.x, wa, accA[4]); accB[4] = ffma2(h45.x, wb, accB[4]);
            accA[5] = ffma2(h45.y, wa, accA[5]); accB[5] = ffma2(h45.y, wb, accB[5]);
            accA[6] = ffma2(h67.x, wa, accA[6]); accB[6] = ffma2(h67.x, wb, accB[6]);
            accA[7] = ffma2(h67.y, wa, accA[7]); accB[7] = ffma2(h67.y, wb, accB[7]);
        }

        // write split-K partials
#pragma unroll
        for (int p = 0; p < 8; p++) {
            float lo, hi;
            unpack2(accA[p], lo, hi);
            rA[(2 * p) * 16] = lo; rA[(2 * p + 1) * 16] = hi;
            unpack2(accB[p], lo, hi);
            rB[(2 * p) * 16] = lo; rB[(2 * p + 1) * 16] = hi;
        }
        __syncthreads();

        // reduce 8 warps + pointwise LSTM cell (fast activations)
        float si = 0.f, sf = 0.f, sg = 0.f, so = 0.f;
#pragma unroll
        for (int w = 0; w < 8; w++) {
            const float* rp = &red[((w * 4) * 16 + bl) * 16 + jl_u];
            si += rp[0];
            sf += rp[256];
            sg += rp[512];
            so += rp[768];
        }
        float gi = si + xi + bi, gf = sf + xf + bf;
        float gg = sg + xg + bg, go = so + xo + bo;
        float iv = fast_sigmoid(gi), fv = fast_sigmoid(gf);
        float gv = fast_tanh(gg),    ov = fast_sigmoid(go);
        cc = fv * cc + iv * gv;
        float hv = ov * fast_tanh(cc);

        // cross-CTA-visible h store first, then output
        __stcg(&g_hT[cur ^ 1][j * BATCH + b], hv);
        out[((size_t)b * SEQ + t) * HSZ + j] = hv;
        if (t == SEQ - 1) {
            out[(size_t)BATCH * SEQ * HSZ + (size_t)b * HSZ + j] = hv;
            out[(size_t)BATCH * SEQ * HSZ + BATCH * HSZ + (size_t)b * HSZ + j] = cc;
        }

        // per-bt-group barrier (32 arrivals, monotonic: replay-safe)
        __syncthreads();
        if (tid == 0) {
            __threadfence();
            unsigned tk = atomicAdd(cnt, 1u) + 1u;
            unsigned target = (tk + (GRP - 1)) & ~(unsigned)(GRP - 1);
            while (*((volatile unsigned*)cnt) < target) { }
            __threadfence();
        }
        __syncthreads();
    }
}

// ---------------- launch ----------------------------------------------------
extern "C" void kernel_launch(void* const* d_in, const int* in_sizes, int n_in,
                              void* d_out, int out_size) {
    const float* x    = (const float*)d_in[0];
    const float* wih  = (const float*)d_in[1];
    const float* whh  = (const float*)d_in[2];
    const float* bias = (const float*)d_in[3];
    const float* h0   = (const float*)d_in[4];
    const float* c0   = (const float*)d_in[5];
    float* out = (float*)d_out;

    const int smem_bytes = 131072 + 32768 + 32768;   // 192KB
    cudaFuncSetAttribute(lstm_persist, cudaFuncAttributeMaxDynamicSharedMemorySize,
                         smem_bytes);

    // 128x128 tiles: grid = (2048/128, 32768/128) = (16, 256)
    xproj_gemm<<<dim3(16, 256), 256>>>(x, wih);
    lstm_persist<<<NCTA, 256, smem_bytes>>>(whh, bias, h0, c0, out);
}